// round 11
// baseline (speedup 1.0000x reference)
#include <cuda_runtime.h>

#define NB     256
#define NQ     1000
#define NC     81
#define QCN    81000
#define TOPK   100
#define CAP    8192          // global candidate capacity per batch
#define CAPF   2048          // fallback shared capacity (kernel C)
#define NTA    1024
#define NTB    256
#define NTC    512
#define QPB    40
#define SPLITB 25
#define NBINA  4096
#define NBINC  4096
#define WLO    110           // sample suffix floor -> >=110 survivors guaranteed
#define SRTN   256           // survivor capacity for rank-emit path

// ---- global scratch (no allocs allowed; zero-initialized at load) ------
__device__ float               g_w1[NB * NQ];
__device__ float               g_w2[NB * NQ];
__device__ float               g_lthr[NB * NQ];
__device__ float               g_thr[NB];
__device__ unsigned            g_thrbits[NB];
__device__ unsigned long long  g_cand[NB * CAP];
__device__ int                 g_cnt[NB];

__device__ __forceinline__ float sigf(float x) {
    return __fdividef(1.0f, 1.0f + __expf(-x));
}

__device__ __forceinline__ void pushg(int b, unsigned long long key) {
    unsigned m = __activemask();
    int lane   = threadIdx.x & 31;
    int leader = __ffs(m) - 1;
    int rank   = __popc(m & ((1u << lane) - 1u));
    int base   = 0;
    if (lane == leader) base = atomicAdd(&g_cnt[b], __popc(m));
    base = __shfl_sync(m, base, leader);
    int pos = base + rank;
    if (pos < CAP) g_cand[b * CAP + pos] = key;  // overflow counts -> fallback
}

__device__ __forceinline__ void pushs(unsigned long long key,
                                      unsigned long long* cand, int* cnt, int cap) {
    unsigned m = __activemask();
    int lane   = threadIdx.x & 31;
    int leader = __ffs(m) - 1;
    int rank   = __popc(m & ((1u << lane) - 1u));
    int base   = 0;
    if (lane == leader) base = atomicAdd(cnt, __popc(m));
    base = __shfl_sync(m, base, leader);
    int pos = base + rank;
    if (pos < cap) cand[pos] = key;
}

// lthr = ln(te/(w1-te)) = (lg2(te) - lg2(w1-te)) * ln2  -- 2 MUFU, no divide
__device__ __forceinline__ float logit_thr(float te, float w1) {
    float d = w1 - te;
    if (d <= te * 1e-6f) return __int_as_float(0x7f800000);  // ~none pass
    float lt = (__log2f(te) - __log2f(d)) * 0.69314718f - 1e-3f;  // slack
    return fmaxf(lt, -20.0f);
}

// find largest bin with suffix_cum >= target; result -> s_out[0]=bin, s_out[1]=cum
template<int NT, int BPT>
__device__ __forceinline__ void suffix_find(const int* binv, int cs, int target,
                                            int* s_wsum, int* s_out) {
    const int NW = NT / 32;
    int tid = threadIdx.x, lane = tid & 31, w = tid >> 5;
    int suf = cs;
#pragma unroll
    for (int off = 1; off < 32; off <<= 1) {
        int v = __shfl_down_sync(0xffffffffu, suf, off);
        if (lane + off < 32) suf += v;
    }
    if (lane == 0) s_wsum[w] = suf;
    __syncthreads();
    int wsuf = 0;
    for (int w2 = w + 1; w2 < NW; w2++) wsuf += s_wsum[w2];
    int sufExcl = wsuf + (suf - cs);     // strictly above this thread's bins
    if (sufExcl < target && sufExcl + cs >= target) {
        int run = sufExcl;
#pragma unroll
        for (int k = BPT - 1; k >= 0; k--) {
            run += binv[k];
            if (run >= target) { s_out[0] = tid * BPT + k; s_out[1] = run; break; }
        }
    }
    __syncthreads();
}

// ======================= Kernel A: weights + threshold ===================
__global__ __launch_bounds__(NTA)
void kernelA(const float* __restrict__ logits,
             const float* __restrict__ obj,
             const float* __restrict__ unk)
{
    __shared__ float s_w1[NQ];
    __shared__ int   s_hist[NBINA];
    __shared__ int   s_wsum[NTA / 32];
    __shared__ int   s_out[2];

    const int b   = blockIdx.x;
    const int tid = threadIdx.x;
    const float* lg = logits + (size_t)b * QCN;

    // issue 2 sample loads FIRST (independent of obj/unk)
    float raw[2];
    int   sq[2];
    bool  ok[2];
#pragma unroll
    for (int k = 0; k < 2; k++) {
        int s = k * NTA + tid;
        int q = s >> 1, c = s & 1;        // every query x classes 0..1
        sq[k] = q;
        ok[k] = (q < NQ);
        raw[k] = ok[k] ? __ldg(&lg[q * NC + c]) : 0.0f;
    }

    if (tid == 0) g_cnt[b] = 0;
#pragma unroll
    for (int k = 0; k < NBINA / NTA; k++) s_hist[k * NTA + tid] = 0;

    float w1v = 0.0f, w2v = 0.0f;
    if (tid < NQ) {
        float w  = __expf(-obj[b * NQ + tid]);
        float su = sigf(unk[b * NQ + tid]);
        w1v = w * (1.0f - su);
        w2v = w * su;
        s_w1[tid] = w1v;
        g_w1[b * NQ + tid] = w1v;
        g_w2[b * NQ + tid] = w2v;
    }
    __syncthreads();

#pragma unroll
    for (int k = 0; k < 2; k++) {
        if (ok[k]) {
            float v = s_w1[sq[k]] * sigf(raw[k]);
            unsigned idx = __float_as_uint(v) >> 19;
            if (idx > NBINA - 1) idx = NBINA - 1;
            atomicAdd(&s_hist[idx], 1);
        }
    }
    __syncthreads();

    int binv[NBINA / NTA], cs = 0;
#pragma unroll
    for (int k = 0; k < NBINA / NTA; k++) {
        binv[k] = s_hist[tid * (NBINA / NTA) + k];
        cs += binv[k];
    }
    suffix_find<NTA, NBINA / NTA>(binv, cs, WLO, s_wsum, s_out);

    unsigned thrbits = (unsigned)s_out[0] << 19;
    float thrf = __uint_as_float(thrbits);
    if (tid == 0) { g_thr[b] = thrf; g_thrbits[b] = thrbits; }
    float te = thrf * 0.9999f;

    if (tid < NQ) {
        g_lthr[b * NQ + tid] = logit_thr(te, w1v);
        if (w2v >= te) {
            unsigned i = (unsigned)(tid * NC + 80);
            pushg(b, ((unsigned long long)__float_as_uint(w2v) << 32) | (~i));
        }
    }
}

// ======================= Kernel B: query-major scan (smem tables) ========
__global__ __launch_bounds__(NTB)
void kernelB(const float* __restrict__ logits)
{
    __shared__ float s_lt[QPB];
    __shared__ float s_w1t[QPB];

    const int b    = blockIdx.y;
    const int qb   = blockIdx.x * QPB;
    const int lane = threadIdx.x & 31;
    const int warp = threadIdx.x >> 5;
    const int tid  = threadIdx.x;
    const float* lg = logits + (size_t)b * QCN;

    if (tid < QPB) {
        s_lt[tid]  = g_lthr[b * NQ + qb + tid];
        s_w1t[tid] = g_w1[b * NQ + qb + tid];
    }
    __syncthreads();

    float v0[5], v1[5], lt[5], w1[5];
    int   qv[5];
#pragma unroll
    for (int j = 0; j < 5; j++) {
        int q = qb + warp + 8 * j;
        qv[j] = q;
        const float* base = lg + q * NC;
        v0[j] = base[lane];                              // classes 0..31
        v1[j] = (lane < 28) ? base[32 + lane] : -1e30f;  // classes 32..59
        int li = warp + 8 * j;
        lt[j] = s_lt[li];                                // LDS broadcast
        w1[j] = s_w1t[li];
    }
#pragma unroll
    for (int j = 0; j < 5; j++) {
        if (v0[j] >= lt[j]) {
            float p = w1[j] * sigf(v0[j]);
            unsigned i = (unsigned)(qv[j] * NC + lane);
            pushg(b, ((unsigned long long)__float_as_uint(p) << 32) | (~i));
        }
        if (v1[j] >= lt[j]) {
            float p = w1[j] * sigf(v1[j]);
            unsigned i = (unsigned)(qv[j] * NC + 32 + lane);
            pushg(b, ((unsigned long long)__float_as_uint(p) << 32) | (~i));
        }
    }
}

// ============ Kernel C: stream-refine + rank-count emit ==================
__global__ __launch_bounds__(NTC)
void kernelC(const float* __restrict__ logits,
             const float* __restrict__ boxes,
             const float* __restrict__ tsizes,
             float* __restrict__ out)
{
    __shared__ unsigned long long s_buf[CAPF];    // 16 KB: hist alias / fallback sort
    __shared__ unsigned long long s_srt[SRTN];    // 2 KB survivors
    __shared__ int   s_wsum[NTC / 32];
    __shared__ int   s_out[2];
    __shared__ int   s_cnt;

    int* s_hist = (int*)s_buf;                    // 4096 ints

    const int b   = blockIdx.x;
    const int tid = threadIdx.x;
    const float* lg = logits + (size_t)b * QCN;

    int n = g_cnt[b];
    int n_sort = 0;

    if (n >= TOPK && n <= CAP) {
        // ---- pass 1: histogram straight from global candidates ----------
        for (int i = tid; i < NBINC; i += NTC) s_hist[i] = 0;
        __syncthreads();
        unsigned base = g_thrbits[b] >> 16;
        for (int t = tid; t < n; t += NTC) {
            unsigned bits = (unsigned)(g_cand[b * CAP + t] >> 32);
            int idx = (int)(bits >> 16) - (int)base;
            idx = (idx < 0) ? 0 : ((idx > NBINC - 1) ? NBINC - 1 : idx);
            atomicAdd(&s_hist[idx], 1);
        }
        __syncthreads();

        int binv[8], cs = 0;
        int t8 = tid * 8;
#pragma unroll
        for (int k = 0; k < 8; k++) { binv[k] = s_hist[t8 + k]; cs += binv[k]; }
        suffix_find<NTC, 8>(binv, cs, TOPK, s_wsum, s_out);

        int bin2 = s_out[0];
        int cum  = s_out[1];
        if (cum <= SRTN) {
            // ---- pass 2: push survivors (L2-hot reload) -----------------
            unsigned thr2 = (bin2 == 0) ? 0u : ((base + (unsigned)bin2) << 16);
            if (tid == 0) s_cnt = 0;
            __syncthreads();
            for (int t = tid; t < n; t += NTC) {
                unsigned long long key = g_cand[b * CAP + t];
                if ((unsigned)(key >> 32) >= thr2)
                    pushs(key, s_srt, &s_cnt, SRTN);
            }
            __syncthreads();
            int m = s_cnt;   // == cum, in [TOPK, SRTN]

            // ---- rank-by-count: no sort, no barriers --------------------
            if (tid < m) {
                unsigned long long my = s_srt[tid];
                int r = 0;
                for (int j = 0; j < m; j++)
                    r += (s_srt[j] > my);        // broadcast LDS
                if (r < TOPK) {
                    float v    = __uint_as_float((unsigned)(my >> 32));
                    unsigned i = ~(unsigned)my;
                    unsigned q = i / NC;
                    unsigned c = i - q * NC;
                    int o = b * TOPK + r;
                    out[o] = v;                               // scores
                    out[NB * TOPK + o] = (float)c;            // labels
                    const float* bx = boxes + ((size_t)(b * NQ + q)) * 4;
                    float cx = bx[0], cy = bx[1], w = bx[2], h = bx[3];
                    float ih = tsizes[b * 2 + 0];
                    float iw = tsizes[b * 2 + 1];
                    float* ob = out + 2 * NB * TOPK + (size_t)o * 4;
                    ob[0] = (cx - 0.5f * w) * iw;
                    ob[1] = (cy - 0.5f * h) * ih;
                    ob[2] = (cx + 0.5f * w) * iw;
                    ob[3] = (cy + 0.5f * h) * ih;
                }
            }
            return;   // normal path done
        }
        // tie pathology: bitonic-sort up to CAPF candidates
        int mm = (n < CAPF) ? n : CAPF;
        __syncthreads();
        for (int t = tid; t < CAPF; t += NTC)
            s_buf[t] = (t < mm) ? g_cand[b * CAP + t] : 0ULL;
        __syncthreads();
        n_sort = CAPF;
    } else {
        // ---- fallback: bounded rescan with retry (dead in practice) -----
        float curthr = g_thr[b];
        if (curthr <= 0.0f) curthr = 1e-6f;
        for (int attempt = 0; attempt < 12; attempt++) {
            if (n < TOPK) curthr *= 0.25f; else curthr *= 4.0f;
            float te = curthr * 0.9999f;
            if (tid == 0) s_cnt = 0;
            __syncthreads();
            for (int i = tid; i < QCN; i += NTC) {
                unsigned q = (unsigned)i / NC;
                int c = i - (int)q * NC;
                float p = -1.0f;
                if (c < 60)       p = g_w1[b * NQ + q] * sigf(lg[i]);
                else if (c == 80) p = g_w2[b * NQ + q];
                if (p >= te)
                    pushs(((unsigned long long)__float_as_uint(p) << 32) |
                          (~(unsigned)i), s_buf, &s_cnt, CAPF);
            }
            __syncthreads();
            n = s_cnt;
            if (n >= TOPK && n <= CAPF) break;
            __syncthreads();
        }
        if (n > CAPF) n = CAPF;
        for (int t = n + tid; t < CAPF; t += NTC) s_buf[t] = 0ULL;
        __syncthreads();
        n_sort = CAPF;
    }

    // ---- bitonic ascending sort (tie/fallback paths only) ---------------
    for (int k = 2; k <= n_sort; k <<= 1)
        for (int j = k >> 1; j > 0; j >>= 1) {
            for (int t = tid; t < n_sort; t += NTC) {
                int x = t ^ j;
                if (x > t) {
                    unsigned long long a = s_buf[t], bb = s_buf[x];
                    bool up = ((t & k) == 0);
                    if (up ? (a > bb) : (a < bb)) { s_buf[t] = bb; s_buf[x] = a; }
                }
            }
            __syncthreads();
        }

    if (tid < TOPK) {
        unsigned long long key = s_buf[n_sort - 1 - tid];
        float v    = __uint_as_float((unsigned)(key >> 32));
        unsigned i = ~(unsigned)key;
        if (key == 0ULL) { v = 0.0f; i = 0; }
        unsigned q = i / NC;
        unsigned c = i - q * NC;
        int o = b * TOPK + tid;
        out[o] = v;
        out[NB * TOPK + o] = (float)c;
        const float* bx = boxes + ((size_t)(b * NQ + q)) * 4;
        float cx = bx[0], cy = bx[1], w = bx[2], h = bx[3];
        float ih = tsizes[b * 2 + 0];
        float iw = tsizes[b * 2 + 1];
        float* ob = out + 2 * NB * TOPK + (size_t)o * 4;
        ob[0] = (cx - 0.5f * w) * iw;
        ob[1] = (cy - 0.5f * h) * ih;
        ob[2] = (cx + 0.5f * w) * iw;
        ob[3] = (cy + 0.5f * h) * ih;
    }
}

extern "C" void kernel_launch(void* const* d_in, const int* in_sizes, int n_in,
                              void* d_out, int out_size) {
    const float* logits = (const float*)d_in[0];
    const float* obj    = (const float*)d_in[1];
    const float* boxes  = (const float*)d_in[2];
    const float* unk    = (const float*)d_in[3];
    const float* ts     = (const float*)d_in[4];
    float* out = (float*)d_out;

    kernelA<<<NB, NTA>>>(logits, obj, unk);
    kernelB<<<dim3(SPLITB, NB), NTB>>>(logits);
    kernelC<<<NB, NTC>>>(logits, boxes, ts, out);
}

// round 12
// speedup vs baseline: 1.3751x; 1.3751x over previous
#include <cuda_runtime.h>

#define NB     256
#define NQ     1000
#define NC     81
#define QCN    81000
#define TOPK   100
#define CAP    16384         // global candidate capacity per batch
#define CAPF   2048          // fallback shared capacity (kernel C)
#define NTA    1024
#define NTB    256
#define NTC    512
#define QPB    40
#define SPLITB 25
#define NBINA  4096
#define NBINC  4096
#define WLO    110           // sample suffix floor -> >=110 survivors guaranteed
#define SRTN   256           // survivor capacity for rank-emit path
#define SROWS  250           // sampled rows per batch (q = 4*idx)

// ---- global scratch (no allocs allowed; zero-initialized at load) ------
__device__ float               g_w1[NB * NQ];
__device__ float               g_w2[NB * NQ];
__device__ float               g_lthr[NB * NQ];
__device__ float               g_thr[NB];
__device__ unsigned            g_thrbits[NB];
__device__ unsigned long long  g_cand[NB * CAP];
__device__ int                 g_cnt[NB];

__device__ __forceinline__ float sigf(float x) {
    return __fdividef(1.0f, 1.0f + __expf(-x));
}

__device__ __forceinline__ void pushg(int b, unsigned long long key) {
    unsigned m = __activemask();
    int lane   = threadIdx.x & 31;
    int leader = __ffs(m) - 1;
    int rank   = __popc(m & ((1u << lane) - 1u));
    int base   = 0;
    if (lane == leader) base = atomicAdd(&g_cnt[b], __popc(m));
    base = __shfl_sync(m, base, leader);
    int pos = base + rank;
    if (pos < CAP) g_cand[b * CAP + pos] = key;  // overflow counts -> fallback
}

__device__ __forceinline__ void pushs(unsigned long long key,
                                      unsigned long long* cand, int* cnt, int cap) {
    unsigned m = __activemask();
    int lane   = threadIdx.x & 31;
    int leader = __ffs(m) - 1;
    int rank   = __popc(m & ((1u << lane) - 1u));
    int base   = 0;
    if (lane == leader) base = atomicAdd(cnt, __popc(m));
    base = __shfl_sync(m, base, leader);
    int pos = base + rank;
    if (pos < cap) cand[pos] = key;
}

// lthr = ln(te/(w1-te)) = (lg2(te) - lg2(w1-te)) * ln2  -- 2 MUFU, no divide
__device__ __forceinline__ float logit_thr(float te, float w1) {
    float d = w1 - te;
    if (d <= te * 1e-6f) return __int_as_float(0x7f800000);  // ~none pass
    float lt = (__log2f(te) - __log2f(d)) * 0.69314718f - 1e-3f;  // slack
    return fmaxf(lt, -20.0f);
}

// find largest bin with suffix_cum >= target; result -> s_out[0]=bin, s_out[1]=cum
template<int NT, int BPT>
__device__ __forceinline__ void suffix_find(const int* binv, int cs, int target,
                                            int* s_wsum, int* s_out) {
    const int NW = NT / 32;
    int tid = threadIdx.x, lane = tid & 31, w = tid >> 5;
    int suf = cs;
#pragma unroll
    for (int off = 1; off < 32; off <<= 1) {
        int v = __shfl_down_sync(0xffffffffu, suf, off);
        if (lane + off < 32) suf += v;
    }
    if (lane == 0) s_wsum[w] = suf;
    __syncthreads();
    int wsuf = 0;
    for (int w2 = w + 1; w2 < NW; w2++) wsuf += s_wsum[w2];
    int sufExcl = wsuf + (suf - cs);     // strictly above this thread's bins
    if (sufExcl < target && sufExcl + cs >= target) {
        int run = sufExcl;
#pragma unroll
        for (int k = BPT - 1; k >= 0; k--) {
            run += binv[k];
            if (run >= target) { s_out[0] = tid * BPT + k; s_out[1] = run; break; }
        }
    }
    __syncthreads();
}

// ======================= Kernel A: weights + threshold ===================
__global__ __launch_bounds__(NTA)
void kernelA(const float* __restrict__ logits,
             const float* __restrict__ obj,
             const float* __restrict__ unk)
{
    __shared__ float s_w1[NQ];
    __shared__ int   s_hist[NBINA];
    __shared__ int   s_wsum[NTA / 32];
    __shared__ int   s_out[2];

    const int b   = blockIdx.x;
    const int tid = threadIdx.x;
    const float* lg = logits + (size_t)b * QCN;

    // 4000 samples from 250 rows x 16 classes (q = 4*idx): only 250 DRAM
    // lines touched instead of 1000. Issued FIRST (independent of obj/unk).
    float raw[4];
    int   sq[4];
    bool  ok[4];
#pragma unroll
    for (int k = 0; k < 4; k++) {
        int s = k * NTA + tid;
        int idx = s >> 4;                 // 0..255
        int q = idx * 4;                  // 0,4,...,1020
        int c = s & 15;                   // classes 0..15 (all valid)
        sq[k] = q;
        ok[k] = (idx < SROWS);
        raw[k] = ok[k] ? __ldg(&lg[q * NC + c]) : 0.0f;
    }

    if (tid == 0) g_cnt[b] = 0;
#pragma unroll
    for (int k = 0; k < NBINA / NTA; k++) s_hist[k * NTA + tid] = 0;

    float w1v = 0.0f, w2v = 0.0f;
    if (tid < NQ) {
        float w  = __expf(-obj[b * NQ + tid]);
        float su = sigf(unk[b * NQ + tid]);
        w1v = w * (1.0f - su);
        w2v = w * su;
        s_w1[tid] = w1v;
        g_w1[b * NQ + tid] = w1v;
        g_w2[b * NQ + tid] = w2v;
    }
    __syncthreads();

#pragma unroll
    for (int k = 0; k < 4; k++) {
        if (ok[k]) {
            float v = s_w1[sq[k]] * sigf(raw[k]);
            unsigned idx = __float_as_uint(v) >> 19;
            if (idx > NBINA - 1) idx = NBINA - 1;
            atomicAdd(&s_hist[idx], 1);
        }
    }
    __syncthreads();

    int binv[NBINA / NTA], cs = 0;
#pragma unroll
    for (int k = 0; k < NBINA / NTA; k++) {
        binv[k] = s_hist[tid * (NBINA / NTA) + k];
        cs += binv[k];
    }
    suffix_find<NTA, NBINA / NTA>(binv, cs, WLO, s_wsum, s_out);

    unsigned thrbits = (unsigned)s_out[0] << 19;
    float thrf = __uint_as_float(thrbits);
    if (tid == 0) { g_thr[b] = thrf; g_thrbits[b] = thrbits; }
    float te = thrf * 0.9999f;

    if (tid < NQ) {
        g_lthr[b * NQ + tid] = logit_thr(te, w1v);
        if (w2v >= te) {
            unsigned i = (unsigned)(tid * NC + 80);
            pushg(b, ((unsigned long long)__float_as_uint(w2v) << 32) | (~i));
        }
    }
}

// ======================= Kernel B: query-major scan (smem tables) ========
__global__ __launch_bounds__(NTB)
void kernelB(const float* __restrict__ logits)
{
    __shared__ float s_lt[QPB];
    __shared__ float s_w1t[QPB];

    const int b    = blockIdx.y;
    const int qb   = blockIdx.x * QPB;
    const int lane = threadIdx.x & 31;
    const int warp = threadIdx.x >> 5;
    const int tid  = threadIdx.x;
    const float* lg = logits + (size_t)b * QCN;

    if (tid < QPB) {
        s_lt[tid]  = g_lthr[b * NQ + qb + tid];
        s_w1t[tid] = g_w1[b * NQ + qb + tid];
    }
    __syncthreads();

    float v0[5], v1[5], lt[5], w1[5];
    int   qv[5];
#pragma unroll
    for (int j = 0; j < 5; j++) {
        int q = qb + warp + 8 * j;
        qv[j] = q;
        const float* base = lg + q * NC;
        v0[j] = base[lane];                              // classes 0..31
        v1[j] = (lane < 28) ? base[32 + lane] : -1e30f;  // classes 32..59
        int li = warp + 8 * j;
        lt[j] = s_lt[li];                                // LDS broadcast
        w1[j] = s_w1t[li];
    }
#pragma unroll
    for (int j = 0; j < 5; j++) {
        if (v0[j] >= lt[j]) {
            float p = w1[j] * sigf(v0[j]);
            unsigned i = (unsigned)(qv[j] * NC + lane);
            pushg(b, ((unsigned long long)__float_as_uint(p) << 32) | (~i));
        }
        if (v1[j] >= lt[j]) {
            float p = w1[j] * sigf(v1[j]);
            unsigned i = (unsigned)(qv[j] * NC + 32 + lane);
            pushg(b, ((unsigned long long)__float_as_uint(p) << 32) | (~i));
        }
    }
}

// ============ Kernel C: stream-refine + rank-count emit ==================
__global__ __launch_bounds__(NTC)
void kernelC(const float* __restrict__ logits,
             const float* __restrict__ boxes,
             const float* __restrict__ tsizes,
             float* __restrict__ out)
{
    __shared__ unsigned long long s_buf[CAPF];    // 16 KB: hist alias / fallback sort
    __shared__ unsigned long long s_srt[SRTN];    // 2 KB survivors
    __shared__ int   s_wsum[NTC / 32];
    __shared__ int   s_out[2];
    __shared__ int   s_cnt;

    int* s_hist = (int*)s_buf;                    // 4096 ints

    const int b   = blockIdx.x;
    const int tid = threadIdx.x;
    const float* lg = logits + (size_t)b * QCN;

    int n = g_cnt[b];
    int n_sort = 0;

    if (n >= TOPK && n <= CAP) {
        // ---- pass 1: histogram straight from global candidates ----------
        for (int i = tid; i < NBINC; i += NTC) s_hist[i] = 0;
        __syncthreads();
        unsigned base = g_thrbits[b] >> 16;
        for (int t = tid; t < n; t += NTC) {
            unsigned bits = (unsigned)(g_cand[b * CAP + t] >> 32);
            int idx = (int)(bits >> 16) - (int)base;
            idx = (idx < 0) ? 0 : ((idx > NBINC - 1) ? NBINC - 1 : idx);
            atomicAdd(&s_hist[idx], 1);
        }
        __syncthreads();

        int binv[8], cs = 0;
        int t8 = tid * 8;
#pragma unroll
        for (int k = 0; k < 8; k++) { binv[k] = s_hist[t8 + k]; cs += binv[k]; }
        suffix_find<NTC, 8>(binv, cs, TOPK, s_wsum, s_out);

        int bin2 = s_out[0];
        int cum  = s_out[1];
        if (cum <= SRTN) {
            // ---- pass 2: push survivors (L2-hot reload) -----------------
            unsigned thr2 = (bin2 == 0) ? 0u : ((base + (unsigned)bin2) << 16);
            if (tid == 0) s_cnt = 0;
            __syncthreads();
            for (int t = tid; t < n; t += NTC) {
                unsigned long long key = g_cand[b * CAP + t];
                if ((unsigned)(key >> 32) >= thr2)
                    pushs(key, s_srt, &s_cnt, SRTN);
            }
            __syncthreads();
            int m = s_cnt;   // == cum, in [TOPK, SRTN]

            // ---- rank-by-count: no sort, no barriers --------------------
            if (tid < m) {
                unsigned long long my = s_srt[tid];
                int r = 0;
                for (int j = 0; j < m; j++)
                    r += (s_srt[j] > my);        // broadcast LDS
                if (r < TOPK) {
                    float v    = __uint_as_float((unsigned)(my >> 32));
                    unsigned i = ~(unsigned)my;
                    unsigned q = i / NC;
                    unsigned c = i - q * NC;
                    int o = b * TOPK + r;
                    out[o] = v;                               // scores
                    out[NB * TOPK + o] = (float)c;            // labels
                    const float* bx = boxes + ((size_t)(b * NQ + q)) * 4;
                    float cx = bx[0], cy = bx[1], w = bx[2], h = bx[3];
                    float ih = tsizes[b * 2 + 0];
                    float iw = tsizes[b * 2 + 1];
                    float* ob = out + 2 * NB * TOPK + (size_t)o * 4;
                    ob[0] = (cx - 0.5f * w) * iw;
                    ob[1] = (cy - 0.5f * h) * ih;
                    ob[2] = (cx + 0.5f * w) * iw;
                    ob[3] = (cy + 0.5f * h) * ih;
                }
            }
            return;   // normal path done
        }
        // tie pathology: bitonic-sort up to CAPF candidates
        int mm = (n < CAPF) ? n : CAPF;
        __syncthreads();
        for (int t = tid; t < CAPF; t += NTC)
            s_buf[t] = (t < mm) ? g_cand[b * CAP + t] : 0ULL;
        __syncthreads();
        n_sort = CAPF;
    } else {
        // ---- fallback: bounded rescan with retry (dead in practice) -----
        float curthr = g_thr[b];
        if (curthr <= 0.0f) curthr = 1e-6f;
        for (int attempt = 0; attempt < 12; attempt++) {
            if (n < TOPK) curthr *= 0.25f; else curthr *= 4.0f;
            float te = curthr * 0.9999f;
            if (tid == 0) s_cnt = 0;
            __syncthreads();
            for (int i = tid; i < QCN; i += NTC) {
                unsigned q = (unsigned)i / NC;
                int c = i - (int)q * NC;
                float p = -1.0f;
                if (c < 60)       p = g_w1[b * NQ + q] * sigf(lg[i]);
                else if (c == 80) p = g_w2[b * NQ + q];
                if (p >= te)
                    pushs(((unsigned long long)__float_as_uint(p) << 32) |
                          (~(unsigned)i), s_buf, &s_cnt, CAPF);
            }
            __syncthreads();
            n = s_cnt;
            if (n >= TOPK && n <= CAPF) break;
            __syncthreads();
        }
        if (n > CAPF) n = CAPF;
        for (int t = n + tid; t < CAPF; t += NTC) s_buf[t] = 0ULL;
        __syncthreads();
        n_sort = CAPF;
    }

    // ---- bitonic ascending sort (tie/fallback paths only) ---------------
    for (int k = 2; k <= n_sort; k <<= 1)
        for (int j = k >> 1; j > 0; j >>= 1) {
            for (int t = tid; t < n_sort; t += NTC) {
                int x = t ^ j;
                if (x > t) {
                    unsigned long long a = s_buf[t], bb = s_buf[x];
                    bool up = ((t & k) == 0);
                    if (up ? (a > bb) : (a < bb)) { s_buf[t] = bb; s_buf[x] = a; }
                }
            }
            __syncthreads();
        }

    if (tid < TOPK) {
        unsigned long long key = s_buf[n_sort - 1 - tid];
        float v    = __uint_as_float((unsigned)(key >> 32));
        unsigned i = ~(unsigned)key;
        if (key == 0ULL) { v = 0.0f; i = 0; }
        unsigned q = i / NC;
        unsigned c = i - q * NC;
        int o = b * TOPK + tid;
        out[o] = v;
        out[NB * TOPK + o] = (float)c;
        const float* bx = boxes + ((size_t)(b * NQ + q)) * 4;
        float cx = bx[0], cy = bx[1], w = bx[2], h = bx[3];
        float ih = tsizes[b * 2 + 0];
        float iw = tsizes[b * 2 + 1];
        float* ob = out + 2 * NB * TOPK + (size_t)o * 4;
        ob[0] = (cx - 0.5f * w) * iw;
        ob[1] = (cy - 0.5f * h) * ih;
        ob[2] = (cx + 0.5f * w) * iw;
        ob[3] = (cy + 0.5f * h) * ih;
    }
}

extern "C" void kernel_launch(void* const* d_in, const int* in_sizes, int n_in,
                              void* d_out, int out_size) {
    const float* logits = (const float*)d_in[0];
    const float* obj    = (const float*)d_in[1];
    const float* boxes  = (const float*)d_in[2];
    const float* unk    = (const float*)d_in[3];
    const float* ts     = (const float*)d_in[4];
    float* out = (float*)d_out;

    kernelA<<<NB, NTA>>>(logits, obj, unk);
    kernelB<<<dim3(SPLITB, NB), NTB>>>(logits);
    kernelC<<<NB, NTC>>>(logits, boxes, ts, out);
}